// round 7
// baseline (speedup 1.0000x reference)
#include <cuda_runtime.h>
#include <cuda_bf16.h>
#include <cstdint>
#include <math.h>

#define NN   50000
#define EE   800000
#define FIN  256
#define HID  256
#define FOUT 128

// ---------------- scratch (device globals; no allocation allowed) ----------
__device__ float g_bufA[4][NN * HID];        // gemm out (fp32) for agg gather
__device__ float g_bufC[4][NN * FOUT];       // layer-2 gemm out for agg2
__device__ uint2 g_xh[4][NN * FIN / 4];      // pre-split x (bf16 hi)
__device__ uint2 g_xl[4][NN * FIN / 4];      // pre-split x (bf16 lo)
__device__ uint2 g_bh[4][NN * HID / 4];      // pre-split hidden (bf16 hi)
__device__ uint2 g_bl[4][NN * HID / 4];      // pre-split hidden (bf16 lo)
__device__ uint16_t g_wth[4 * 65536 + 6 * 32768];  // W^T hi
__device__ uint16_t g_wtl[4 * 65536 + 6 * 32768];  // W^T lo
__device__ float g_dinv[4][NN];
__device__ float g_deginv[4][NN];
__device__ int   g_counts[4][NN];
__device__ int   g_cursor[4][NN];
__device__ int   g_rowptr[4][NN + 1];
__device__ int   g_col[4][EE];
__device__ float g_coef[4][EE];
__device__ int   g_fmt64;

struct Ptr4 { const float* p[4]; };

// ==================== helpers ================================================
__device__ __forceinline__ void cp16(uint32_t dst, const void* src, int nbytes) {
    asm volatile("cp.async.cg.shared.global [%0], [%1], 16, %2;"
                 :: "r"(dst), "l"(src), "r"(nbytes));
}

__device__ __forceinline__ void mma_bf16(float* d, const uint32_t* a, const uint32_t* b) {
    asm volatile(
        "mma.sync.aligned.m16n8k16.row.col.f32.bf16.bf16.f32 "
        "{%0,%1,%2,%3}, {%4,%5,%6,%7}, {%8,%9}, {%0,%1,%2,%3};"
        : "+f"(d[0]), "+f"(d[1]), "+f"(d[2]), "+f"(d[3])
        : "r"(a[0]), "r"(a[1]), "r"(a[2]), "r"(a[3]), "r"(b[0]), "r"(b[1]));
}

// pack {low half = x, high half = y} into bf16x2
__device__ __forceinline__ uint32_t pack_bf16(float x, float y) {
    uint32_t r;
    asm("cvt.rn.bf16x2.f32 %0, %1, %2;" : "=r"(r) : "f"(y), "f"(x));
    return r;
}
__device__ __forceinline__ float bfLO(uint32_t w) { return __uint_as_float(w << 16); }
__device__ __forceinline__ float bfHI(uint32_t w) { return __uint_as_float(w & 0xffff0000u); }

__device__ __forceinline__ uint32_t smem_u32(const void* p) {
    uint32_t a;
    asm("{ .reg .u64 t; cvta.to.shared.u64 t, %1; cvt.u32.u64 %0, t; }"
        : "=r"(a) : "l"(p));
    return a;
}

// ==================== pre-split bf16 GEMM (mma.sync, sm_80+ PTX) ============
// C[M,NC] = A[M,256] @ W^T, operands pre-split into bf16 hi/lo arrays.
// CTA tile 128x128, BK=32, 8 warps (4M x 2N), 3 MMAs per frag (hi*hi + cross).
// Mainloop: pure LDS + HMMA (no cvt). Smem word-stride 20: conflict-free.

#define LDW 20                        // words per row (16 data + 4 pad)
#define TILE_WORDS (128 * LDW)        // 2560 words = 10240 B per region
#define SMEM_GEMM (2 * 4 * TILE_WORDS * 4)  // 2 bufs x {Ah,Al,Bh,Bl} = 81920 B

struct GArgs {
    const uint16_t *ah[6], *al[6], *wh[6], *wl[6];
    float* c[6];
};

template<int NC>
__global__ void __launch_bounds__(256, 1)
k_gemm(GArgs g, int M)
{
    const int z = blockIdx.z;
    const uint16_t* __restrict__ Ah = g.ah[z];
    const uint16_t* __restrict__ Al = g.al[z];
    const uint16_t* __restrict__ Wh = g.wh[z];
    const uint16_t* __restrict__ Wl = g.wl[z];
    float* __restrict__ C = g.c[z];

    extern __shared__ uint32_t smw[];
    const uint32_t sbase = smem_u32(smw);

    const int tid  = threadIdx.x;
    const int warp = tid >> 5, lane = tid & 31;
    const int wm = (warp & 3) * 32;
    const int wn = (warp >> 2) * 64;
    const int r  = lane >> 2, c = lane & 3;
    const int bm  = blockIdx.x * 128;
    const int bn0 = blockIdx.y * 128;

    float acc[2][8][4];
    #pragma unroll
    for (int t = 0; t < 2; t++)
        #pragma unroll
        for (int u = 0; u < 8; u++)
            #pragma unroll
            for (int i = 0; i < 4; i++) acc[t][u][i] = 0.f;

    // loader: 2048 cp16 per tile = 8 per thread.
    // region = i>>1 (0=Ah,1=Al,2=Bh,3=Bl); row = ((i&1)*256+tid)>>2; c16 = tid&3
    auto load_tile = [&](int kt, int buf) {
        const int kcol = kt * 32;     // element column
        #pragma unroll
        for (int i = 0; i < 8; i++) {
            const int region = i >> 1;
            const int rem = (i & 1) * 256 + tid;
            const int row = rem >> 2;
            const int c16 = tid & 3;
            uint32_t dst = sbase +
                ((uint32_t)((buf * 4 + region) * TILE_WORDS + row * LDW + c16 * 4)) * 4;
            const uint16_t* src;
            int nb = 16;
            if (region < 2) {
                const int grow = bm + row;
                const int rowok = (grow < M) ? grow : 0;
                nb = (grow < M) ? 16 : 0;
                src = (region == 0 ? Ah : Al) + (size_t)rowok * 256 + kcol + c16 * 8;
            } else {
                src = (region == 2 ? Wh : Wl) + (size_t)(bn0 + row) * 256 + kcol + c16 * 8;
            }
            cp16(dst, src, nb);
        }
    };

    load_tile(0, 0);
    asm volatile("cp.async.commit_group;" ::: "memory");
    load_tile(1, 1);
    asm volatile("cp.async.commit_group;" ::: "memory");

    #pragma unroll 1
    for (int kt = 0; kt < 8; kt++) {
        asm volatile("cp.async.wait_group 1;" ::: "memory");
        __syncthreads();

        const int buf = kt & 1;
        const uint32_t* Abh = smw + (buf * 4 + 0) * TILE_WORDS;
        const uint32_t* Abl = smw + (buf * 4 + 1) * TILE_WORDS;
        const uint32_t* Bbh = smw + (buf * 4 + 2) * TILE_WORDS;
        const uint32_t* Bbl = smw + (buf * 4 + 3) * TILE_WORDS;

        #pragma unroll
        for (int ks = 0; ks < 2; ks++) {
            const int kk = ks * 8;    // word offset within row
            uint32_t afh[2][4], afl[2][4], bfh[8][2], bfl[8][2];
            #pragma unroll
            for (int t = 0; t < 2; t++) {
                const int base = (wm + t * 16 + r) * LDW + kk + c;
                afh[t][0] = Abh[base];
                afh[t][1] = Abh[base + 8 * LDW];
                afh[t][2] = Abh[base + 4];
                afh[t][3] = Abh[base + 8 * LDW + 4];
                afl[t][0] = Abl[base];
                afl[t][1] = Abl[base + 8 * LDW];
                afl[t][2] = Abl[base + 4];
                afl[t][3] = Abl[base + 8 * LDW + 4];
            }
            #pragma unroll
            for (int u = 0; u < 8; u++) {
                const int bb = (wn + u * 8 + r) * LDW + kk + c;
                bfh[u][0] = Bbh[bb];
                bfh[u][1] = Bbh[bb + 4];
                bfl[u][0] = Bbl[bb];
                bfl[u][1] = Bbl[bb + 4];
            }
            #pragma unroll
            for (int t = 0; t < 2; t++)
                #pragma unroll
                for (int u = 0; u < 8; u++) {
                    mma_bf16(acc[t][u], afl[t], bfh[u]);   // lo*hi
                    mma_bf16(acc[t][u], afh[t], bfl[u]);   // hi*lo
                    mma_bf16(acc[t][u], afh[t], bfh[u]);   // hi*hi
                }
        }
        __syncthreads();
        if (kt + 2 < 8) load_tile(kt + 2, buf);
        asm volatile("cp.async.commit_group;" ::: "memory");
    }

    // ---- epilogue ----
    #pragma unroll
    for (int t = 0; t < 2; t++) {
        const int row0 = bm + wm + t * 16 + r;
        #pragma unroll
        for (int u = 0; u < 8; u++) {
            const int col = bn0 + wn + u * 8 + 2 * c;
            if (row0 < M)
                *(float2*)(C + (size_t)row0 * NC + col) =
                    make_float2(acc[t][u][0], acc[t][u][1]);
            if (row0 + 8 < M)
                *(float2*)(C + (size_t)(row0 + 8) * NC + col) =
                    make_float2(acc[t][u][2], acc[t][u][3]);
        }
    }
}

// ---------------- split x into bf16 hi/lo -----------------------------------
__global__ void k_splitx(Ptr4 xs) {
    const int view = blockIdx.y;
    const int i = blockIdx.x * blockDim.x + threadIdx.x;
    if (i >= NN * FIN / 4) return;
    float4 v = ((const float4*)xs.p[view])[i];
    uint32_t h0 = pack_bf16(v.x, v.y);
    uint32_t h1 = pack_bf16(v.z, v.w);
    uint32_t l0 = pack_bf16(v.x - bfLO(h0), v.y - bfHI(h0));
    uint32_t l1 = pack_bf16(v.z - bfLO(h1), v.w - bfHI(h1));
    g_xh[view][i] = make_uint2(h0, h1);
    g_xl[view][i] = make_uint2(l0, l1);
}

// ---------------- batched weight transpose + split ---------------------------
struct TPars {
    const float* src[10];
    int K[10], N[10], dstOff[10];
};
__global__ void k_transpose_all(TPars p) {
    const int m = blockIdx.y;
    const int K = p.K[m], Ncols = p.N[m];
    const float* src = p.src[m];
    uint16_t* dh = g_wth + p.dstOff[m];
    uint16_t* dl = g_wtl + p.dstOff[m];
    const int tot = K * Ncols;
    for (int i = blockIdx.x * blockDim.x + threadIdx.x; i < tot;
         i += gridDim.x * blockDim.x) {
        int k = i / Ncols, n = i % Ncols;
        float v = src[i];
        __nv_bfloat16 hb = __float2bfloat16(v);
        float hf = __bfloat162float(hb);
        __nv_bfloat16 lb = __float2bfloat16(v - hf);
        dh[n * K + k] = *(uint16_t*)&hb;
        dl[n * K + k] = *(uint16_t*)&lb;
    }
}

// ---------------- edge dtype sniff -----------------------------------------
__global__ void k_detect(const int* e32) {
    __shared__ int nz;
    if (threadIdx.x == 0) nz = 0;
    __syncthreads();
    for (int i = threadIdx.x; i < 2048; i += blockDim.x) {
        if (e32[2 * i + 1] != 0) nz = 1;
    }
    __syncthreads();
    if (threadIdx.x == 0) g_fmt64 = (nz == 0) ? 1 : 0;
}

__device__ __forceinline__ int edge_at(const void* e, int idx) {
    if (g_fmt64) return (int)((const long long*)e)[idx];
    return ((const int*)e)[idx];
}

// ---------------- CSR build (batched over 4 relations) ----------------------
struct EPtr4 { const void* e[4]; };

__global__ void k_zero_counts() {
    int i = blockIdx.x * blockDim.x + threadIdx.x;
    if (i < NN) g_counts[blockIdx.y][i] = 0;
}

__global__ void k_count(EPtr4 ep) {
    int i = blockIdx.x * blockDim.x + threadIdx.x;
    if (i >= EE) return;
    int d = edge_at(ep.e[blockIdx.y], EE + i);
    atomicAdd(&g_counts[blockIdx.y][d], 1);
}

__global__ void k_deg() {
    int i = blockIdx.x * blockDim.x + threadIdx.x;
    if (i < NN) {
        int v = blockIdx.y;
        float dg = (float)(g_counts[v][i] + 1);   // +1 self loop
        g_dinv[v][i]   = rsqrtf(dg);
        g_deginv[v][i] = 1.0f / dg;
    }
}

__global__ void k_scan() {
    const int v = blockIdx.x;
    __shared__ int sh[1024];
    __shared__ int carry;
    if (threadIdx.x == 0) { carry = 0; g_rowptr[v][0] = 0; }
    __syncthreads();
    for (int base = 0; base < NN; base += 1024) {
        int i = base + threadIdx.x;
        int val = (i < NN) ? g_counts[v][i] : 0;
        sh[threadIdx.x] = val;
        __syncthreads();
        for (int d = 1; d < 1024; d <<= 1) {
            int t = (threadIdx.x >= d) ? sh[threadIdx.x - d] : 0;
            __syncthreads();
            sh[threadIdx.x] += t;
            __syncthreads();
        }
        if (i < NN) {
            g_rowptr[v][i + 1] = carry + sh[threadIdx.x];
            g_cursor[v][i] = 0;
        }
        __syncthreads();
        if (threadIdx.x == 0) carry += sh[1023];
        __syncthreads();
    }
}

__global__ void k_fill(EPtr4 ep) {
    int i = blockIdx.x * blockDim.x + threadIdx.x;
    if (i >= EE) return;
    const int v = blockIdx.y;
    int s = edge_at(ep.e[v], i);
    int d = edge_at(ep.e[v], EE + i);
    int pos = g_rowptr[v][d] + atomicAdd(&g_cursor[v][d], 1);
    g_col[v][pos]  = s;
    g_coef[v][pos] = g_dinv[v][s] * g_dinv[v][d];
}

// ---------------- GCN aggregation + self loop + bias + LeakyReLU ------------
// SPLIT=true: write bf16 hi/lo (layer-1 hidden, feeds next GEMM)
// SPLIT=false: write fp32 (final per-view outputs)
template <int F, bool SPLIT>
__global__ void __launch_bounds__(256)
k_agg(const float* __restrict__ xwBase, Ptr4 bias, float* __restrict__ outBase) {
    constexpr int TPR = F / 4;
    constexpr int RPB = 256 / TPR;
    const int view = blockIdx.y;
    const int rid = threadIdx.x / TPR;
    const int f4  = threadIdx.x % TPR;
    const int row = blockIdx.x * RPB + rid;
    if (row >= NN) return;

    const float* __restrict__ xw = xwBase + (size_t)view * NN * F;
    const int* __restrict__ rp   = g_rowptr[view];
    const int* __restrict__ col  = g_col[view];
    const float* __restrict__ cf = g_coef[view];

    const int start = rp[row];
    const int end   = rp[row + 1];
    float4 acc = make_float4(0.f, 0.f, 0.f, 0.f);
    for (int p = start; p < end; p++) {
        const int s    = col[p];
        const float w  = cf[p];
        float4 v = *(const float4*)(xw + (size_t)s * F + f4 * 4);
        acc.x += v.x * w; acc.y += v.y * w;
        acc.z += v.z * w; acc.w += v.w * w;
    }
    const float di = g_deginv[view][row];
    float4 sv = *(const float4*)(xw + (size_t)row * F + f4 * 4);
    float4 bv = *(const float4*)(bias.p[view] + f4 * 4);
    float4 o;
    o.x = acc.x + sv.x * di + bv.x;
    o.y = acc.y + sv.y * di + bv.y;
    o.z = acc.z + sv.z * di + bv.z;
    o.w = acc.w + sv.w * di + bv.w;
    o.x = (o.x >= 0.f) ? o.x : 0.2f * o.x;
    o.y = (o.y >= 0.f) ? o.y : 0.2f * o.y;
    o.z = (o.z >= 0.f) ? o.z : 0.2f * o.z;
    o.w = (o.w >= 0.f) ? o.w : 0.2f * o.w;

    if (SPLIT) {
        uint32_t h0 = pack_bf16(o.x, o.y);
        uint32_t h1 = pack_bf16(o.z, o.w);
        uint32_t l0 = pack_bf16(o.x - bfLO(h0), o.y - bfHI(h0));
        uint32_t l1 = pack_bf16(o.z - bfLO(h1), o.w - bfHI(h1));
        const size_t idx = (size_t)row * (F / 4) + f4;
        g_bh[view][idx] = make_uint2(h0, h1);
        g_bl[view][idx] = make_uint2(l0, l1);
    } else {
        float* __restrict__ out = outBase + (size_t)view * NN * F;
        *(float4*)(out + (size_t)row * F + f4 * 4) = o;
    }
}

// ---------------- final combine (batched over 2 node types) ----------------
__global__ void k_combine(const float* __restrict__ outSecs,
                          Ptr4 rbias, float* __restrict__ dst) {
    const int j = blockIdx.y;
    const size_t SEC = (size_t)NN * FOUT;
    const float* jv  = outSecs + (2 + j) * SEC;
    const float* bv  = outSecs + (4 + j) * SEC;
    const float* res = g_bufA[j];              // residual gemm output
    int i = blockIdx.x * blockDim.x + threadIdx.x;
    if (i < NN * FOUT) {
        dst[j * SEC + i] = 0.5f * (jv[i] + bv[i]) + res[i]
                         + rbias.p[j][i & (FOUT - 1)];
    }
}

// ---------------- host orchestration ----------------------------------------
#define GEMM_GRID_X ((NN + 127) / 128)

extern "C" void kernel_launch(void* const* d_in, const int* in_sizes, int n_in,
                              void* d_out, int out_size) {
    const float* x_lj = (const float*)d_in[0];
    const float* x_pj = (const float*)d_in[1];
    const float* x_lb = (const float*)d_in[2];
    const float* x_pb = (const float*)d_in[3];

    EPtr4 ep; ep.e[0] = d_in[4]; ep.e[1] = d_in[5]; ep.e[2] = d_in[6]; ep.e[3] = d_in[7];

    const float* W_j1_l = (const float*)d_in[8];   const float* b_j1_l = (const float*)d_in[9];
    const float* W_j1_p = (const float*)d_in[10];  const float* b_j1_p = (const float*)d_in[11];
    const float* W_j2_l = (const float*)d_in[12];  const float* b_j2_l = (const float*)d_in[13];
    const float* W_j2_p = (const float*)d_in[14];  const float* b_j2_p = (const float*)d_in[15];
    const float* W_b1_l = (const float*)d_in[16];  const float* b_b1_l = (const float*)d_in[17];
    const float* W_b1_p = (const float*)d_in[18];  const float* b_b1_p = (const float*)d_in[19];
    const float* W_b2_l = (const float*)d_in[20];  const float* b_b2_l = (const float*)d_in[21];
    const float* W_b2_p = (const float*)d_in[22];  const float* b_b2_p = (const float*)d_in[23];
    const float* W_r_l  = (const float*)d_in[24];  const float* b_r_l  = (const float*)d_in[25];
    const float* W_r_p  = (const float*)d_in[26];  const float* b_r_p  = (const float*)d_in[27];

    float* out = (float*)d_out;
    const size_t SEC = (size_t)NN * FOUT;

    float *bufA, *bufC;
    uint16_t *xh, *xl, *bh, *bl, *wth, *wtl;
    cudaGetSymbolAddress((void**)&bufA, g_bufA);
    cudaGetSymbolAddress((void**)&bufC, g_bufC);
    cudaGetSymbolAddress((void**)&xh,   g_xh);
    cudaGetSymbolAddress((void**)&xl,   g_xl);
    cudaGetSymbolAddress((void**)&bh,   g_bh);
    cudaGetSymbolAddress((void**)&bl,   g_bl);
    cudaGetSymbolAddress((void**)&wth,  g_wth);
    cudaGetSymbolAddress((void**)&wtl,  g_wtl);

    cudaFuncSetAttribute(k_gemm<256>, cudaFuncAttributeMaxDynamicSharedMemorySize, SMEM_GEMM);
    cudaFuncSetAttribute(k_gemm<128>, cudaFuncAttributeMaxDynamicSharedMemorySize, SMEM_GEMM);

    // view order: 0=jl, 1=jp, 2=bl, 3=bp

    // 1) edge dtype
    k_detect<<<1, 256>>>((const int*)ep.e[0]);

    // 2) CSR build, batched
    dim3 gz((NN + 255) / 256, 4);
    dim3 ge((EE + 255) / 256, 4);
    k_zero_counts<<<gz, 256>>>();
    k_count<<<ge, 256>>>(ep);
    k_deg<<<gz, 256>>>();
    k_scan<<<4, 1024>>>();
    k_fill<<<ge, 256>>>(ep);

    // 3) split x into bf16 hi/lo
    Ptr4 ax; ax.p[0] = x_lj; ax.p[1] = x_pj; ax.p[2] = x_lb; ax.p[3] = x_pb;
    k_splitx<<<dim3((NN * FIN / 4 + 255) / 256, 4), 256>>>(ax);

    // 4) weight transposes + split
    TPars tp;
    const float* ws[10] = {W_j1_l, W_j1_p, W_b1_l, W_b1_p,
                           W_j2_l, W_j2_p, W_b2_l, W_b2_p, W_r_l, W_r_p};
    for (int m = 0; m < 10; m++) {
        tp.src[m] = ws[m];
        tp.K[m] = 256;
        tp.N[m] = (m < 4) ? 256 : 128;
        tp.dstOff[m] = (m < 4) ? m * 65536 : 4 * 65536 + (m - 4) * 32768;
    }
    k_transpose_all<<<dim3(64, 10), 256>>>(tp);

    // 5) layer-1 GEMMs, all 4 views (A = split x, W = j1/b1 set)
    GArgs g1;
    for (int v = 0; v < 4; v++) {
        g1.ah[v] = xh + (size_t)v * NN * FIN;
        g1.al[v] = xl + (size_t)v * NN * FIN;
        g1.wh[v] = wth + v * 65536;
        g1.wl[v] = wtl + v * 65536;
        g1.c[v]  = bufA + (size_t)v * NN * HID;
    }
    g1.ah[4] = g1.ah[5] = g1.ah[0]; g1.al[4] = g1.al[5] = g1.al[0];
    g1.wh[4] = g1.wh[5] = g1.wh[0]; g1.wl[4] = g1.wl[5] = g1.wl[0];
    g1.c[4] = g1.c[5] = g1.c[0];
    k_gemm<256><<<dim3(GEMM_GRID_X, 2, 4), 256, SMEM_GEMM>>>(g1, NN);

    // 6) agg layer 1 -> split bf16 hidden
    Ptr4 b1; b1.p[0] = b_j1_l; b1.p[1] = b_j1_p; b1.p[2] = b_b1_l; b1.p[3] = b_b1_p;
    k_agg<HID, true><<<dim3((NN + 3) / 4, 4), 256>>>(bufA, b1, nullptr);

    // 7) layer-2 GEMMs + residual GEMMs, merged (z = 6)
    GArgs g2;
    for (int v = 0; v < 4; v++) {
        g2.ah[v] = bh + (size_t)v * NN * HID;
        g2.al[v] = bl + (size_t)v * NN * HID;
        g2.wh[v] = wth + 4 * 65536 + v * 32768;
        g2.wl[v] = wtl + 4 * 65536 + v * 32768;
        g2.c[v]  = bufC + (size_t)v * NN * FOUT;
    }
    for (int j = 0; j < 2; j++) {       // residual: A = x_lj / x_pj
        g2.ah[4 + j] = xh + (size_t)j * NN * FIN;
        g2.al[4 + j] = xl + (size_t)j * NN * FIN;
        g2.wh[4 + j] = wth + 4 * 65536 + (4 + j) * 32768;
        g2.wl[4 + j] = wtl + 4 * 65536 + (4 + j) * 32768;
        g2.c[4 + j]  = bufA + (size_t)j * NN * HID;   // bufA free after agg1
    }
    k_gemm<128><<<dim3(GEMM_GRID_X, 1, 6), 256, SMEM_GEMM>>>(g2, NN);

    // 8) agg layer 2 -> output sections 2..5 (jl, jp, bl, bp)
    Ptr4 b2; b2.p[0] = b_j2_l; b2.p[1] = b_j2_p; b2.p[2] = b_b2_l; b2.p[3] = b_b2_p;
    k_agg<FOUT, false><<<dim3((NN + 7) / 8, 4), 256>>>(bufC, b2, out + 2 * SEC);

    // 9) combine
    Ptr4 rb; rb.p[0] = b_r_l; rb.p[1] = b_r_p; rb.p[2] = b_r_l; rb.p[3] = b_r_p;
    k_combine<<<dim3((NN * FOUT + 255) / 256, 2), 256>>>(out, rb, out);
}

// round 8
// speedup vs baseline: 1.0112x; 1.0112x over previous
#include <cuda_runtime.h>
#include <cuda_bf16.h>
#include <cstdint>
#include <math.h>

#define NN   50000
#define EE   800000
#define FIN  256
#define HID  256
#define FOUT 128

// ---------------- scratch (device globals; no allocation allowed) ----------
__device__ float g_bufA[4][NN * HID];        // gemm1 out (fp32); [0],[2] reused for residual
__device__ float g_bufC[4][NN * FOUT];       // layer-2 gemm out for agg2
__device__ uint2 g_xh[4][NN * FIN / 4];      // pre-split x (bf16 hi)
__device__ uint2 g_xl[4][NN * FIN / 4];      // pre-split x (bf16 lo)
__device__ uint2 g_bh[4][NN * HID / 4];      // pre-split hidden (bf16 hi)
__device__ uint2 g_bl[4][NN * HID / 4];      // pre-split hidden (bf16 lo)
__device__ uint16_t g_wth[4 * 65536 + 6 * 32768];  // W^T hi
__device__ uint16_t g_wtl[4 * 65536 + 6 * 32768];  // W^T lo
__device__ float g_dinv[4][NN];
__device__ float g_deginv[4][NN];
__device__ int   g_counts[4][NN];
__device__ int   g_cursor[4][NN];
__device__ int   g_rowptr[4][NN + 1];
__device__ int   g_col[4][EE];
__device__ float g_coef[4][EE];
__device__ int   g_fmt64;

struct Ptr4 { const float* p[4]; };

// ==================== helpers ================================================
__device__ __forceinline__ void cp16(uint32_t dst, const void* src, int nbytes) {
    asm volatile("cp.async.cg.shared.global [%0], [%1], 16, %2;"
                 :: "r"(dst), "l"(src), "r"(nbytes));
}

__device__ __forceinline__ void mma_bf16(float* d, const uint32_t* a, const uint32_t* b) {
    asm volatile(
        "mma.sync.aligned.m16n8k16.row.col.f32.bf16.bf16.f32 "
        "{%0,%1,%2,%3}, {%4,%5,%6,%7}, {%8,%9}, {%0,%1,%2,%3};"
        : "+f"(d[0]), "+f"(d[1]), "+f"(d[2]), "+f"(d[3])
        : "r"(a[0]), "r"(a[1]), "r"(a[2]), "r"(a[3]), "r"(b[0]), "r"(b[1]));
}

__device__ __forceinline__ uint32_t pack_bf16(float x, float y) {
    uint32_t r;
    asm("cvt.rn.bf16x2.f32 %0, %1, %2;" : "=r"(r) : "f"(y), "f"(x));
    return r;
}
__device__ __forceinline__ float bfLO(uint32_t w) { return __uint_as_float(w << 16); }
__device__ __forceinline__ float bfHI(uint32_t w) { return __uint_as_float(w & 0xffff0000u); }

__device__ __forceinline__ uint32_t smem_u32(const void* p) {
    uint32_t a;
    asm("{ .reg .u64 t; cvta.to.shared.u64 t, %1; cvt.u32.u64 %0, t; }"
        : "=r"(a) : "l"(p));
    return a;
}

// ==================== pre-split bf16 GEMM (mma.sync, sm_80+ PTX) ============
#define LDW 20
#define TILE_WORDS (128 * LDW)
#define SMEM_GEMM (2 * 4 * TILE_WORDS * 4)   // 81920 B

struct GArgs {
    const uint16_t *ah[3], *al[3], *wh[3], *wl[3];
    float* c[3];
};

template<int NC>
__global__ void __launch_bounds__(256, 1)
k_gemm(GArgs g, int M)
{
    const int z = blockIdx.z;
    const uint16_t* __restrict__ Ah = g.ah[z];
    const uint16_t* __restrict__ Al = g.al[z];
    const uint16_t* __restrict__ Wh = g.wh[z];
    const uint16_t* __restrict__ Wl = g.wl[z];
    float* __restrict__ C = g.c[z];

    extern __shared__ uint32_t smw[];
    const uint32_t sbase = smem_u32(smw);

    const int tid  = threadIdx.x;
    const int warp = tid >> 5, lane = tid & 31;
    const int wm = (warp & 3) * 32;
    const int wn = (warp >> 2) * 64;
    const int r  = lane >> 2, c = lane & 3;
    const int bm  = blockIdx.x * 128;
    const int bn0 = blockIdx.y * 128;

    float acc[2][8][4];
    #pragma unroll
    for (int t = 0; t < 2; t++)
        #pragma unroll
        for (int u = 0; u < 8; u++)
            #pragma unroll
            for (int i = 0; i < 4; i++) acc[t][u][i] = 0.f;

    auto load_tile = [&](int kt, int buf) {
        const int kcol = kt * 32;
        #pragma unroll
        for (int i = 0; i < 8; i++) {
            const int region = i >> 1;
            const int rem = (i & 1) * 256 + tid;
            const int row = rem >> 2;
            const int c16 = tid & 3;
            uint32_t dst = sbase +
                ((uint32_t)((buf * 4 + region) * TILE_WORDS + row * LDW + c16 * 4)) * 4;
            const uint16_t* src;
            int nb = 16;
            if (region < 2) {
                const int grow = bm + row;
                const int rowok = (grow < M) ? grow : 0;
                nb = (grow < M) ? 16 : 0;
                src = (region == 0 ? Ah : Al) + (size_t)rowok * 256 + kcol + c16 * 8;
            } else {
                src = (region == 2 ? Wh : Wl) + (size_t)(bn0 + row) * 256 + kcol + c16 * 8;
            }
            cp16(dst, src, nb);
        }
    };

    load_tile(0, 0);
    asm volatile("cp.async.commit_group;" ::: "memory");
    load_tile(1, 1);
    asm volatile("cp.async.commit_group;" ::: "memory");

    #pragma unroll 1
    for (int kt = 0; kt < 8; kt++) {
        asm volatile("cp.async.wait_group 1;" ::: "memory");
        __syncthreads();

        const int buf = kt & 1;
        const uint32_t* Abh = smw + (buf * 4 + 0) * TILE_WORDS;
        const uint32_t* Abl = smw + (buf * 4 + 1) * TILE_WORDS;
        const uint32_t* Bbh = smw + (buf * 4 + 2) * TILE_WORDS;
        const uint32_t* Bbl = smw + (buf * 4 + 3) * TILE_WORDS;

        #pragma unroll
        for (int ks = 0; ks < 2; ks++) {
            const int kk = ks * 8;
            uint32_t afh[2][4], afl[2][4], bfh[8][2], bfl[8][2];
            #pragma unroll
            for (int t = 0; t < 2; t++) {
                const int base = (wm + t * 16 + r) * LDW + kk + c;
                afh[t][0] = Abh[base];
                afh[t][1] = Abh[base + 8 * LDW];
                afh[t][2] = Abh[base + 4];
                afh[t][3] = Abh[base + 8 * LDW + 4];
                afl[t][0] = Abl[base];
                afl[t][1] = Abl[base + 8 * LDW];
                afl[t][2] = Abl[base + 4];
                afl[t][3] = Abl[base + 8 * LDW + 4];
            }
            #pragma unroll
            for (int u = 0; u < 8; u++) {
                const int bb = (wn + u * 8 + r) * LDW + kk + c;
                bfh[u][0] = Bbh[bb];
                bfh[u][1] = Bbh[bb + 4];
                bfl[u][0] = Bbl[bb];
                bfl[u][1] = Bbl[bb + 4];
            }
            #pragma unroll
            for (int t = 0; t < 2; t++)
                #pragma unroll
                for (int u = 0; u < 8; u++) {
                    mma_bf16(acc[t][u], afl[t], bfh[u]);
                    mma_bf16(acc[t][u], afh[t], bfl[u]);
                    mma_bf16(acc[t][u], afh[t], bfh[u]);
                }
        }
        __syncthreads();
        if (kt + 2 < 8) load_tile(kt + 2, buf);
        asm volatile("cp.async.commit_group;" ::: "memory");
    }

    #pragma unroll
    for (int t = 0; t < 2; t++) {
        const int row0 = bm + wm + t * 16 + r;
        #pragma unroll
        for (int u = 0; u < 8; u++) {
            const int col = bn0 + wn + u * 8 + 2 * c;
            if (row0 < M)
                *(float2*)(C + (size_t)row0 * NC + col) =
                    make_float2(acc[t][u][0], acc[t][u][1]);
            if (row0 + 8 < M)
                *(float2*)(C + (size_t)(row0 + 8) * NC + col) =
                    make_float2(acc[t][u][2], acc[t][u][3]);
        }
    }
}

// ---------------- split x into bf16 hi/lo -----------------------------------
__global__ void k_splitx(Ptr4 xs) {
    const int view = blockIdx.y;
    const int i = blockIdx.x * blockDim.x + threadIdx.x;
    if (i >= NN * FIN / 4) return;
    float4 v = ((const float4*)xs.p[view])[i];
    uint32_t h0 = pack_bf16(v.x, v.y);
    uint32_t h1 = pack_bf16(v.z, v.w);
    uint32_t l0 = pack_bf16(v.x - bfLO(h0), v.y - bfHI(h0));
    uint32_t l1 = pack_bf16(v.z - bfLO(h1), v.w - bfHI(h1));
    g_xh[view][i] = make_uint2(h0, h1);
    g_xl[view][i] = make_uint2(l0, l1);
}

// ---------------- batched weight transpose + split ---------------------------
struct TPars {
    const float* src[10];
    int K[10], N[10], dstOff[10];
};
__global__ void k_transpose_all(TPars p) {
    const int m = blockIdx.y;
    const int K = p.K[m], Ncols = p.N[m];
    const float* src = p.src[m];
    uint16_t* dh = g_wth + p.dstOff[m];
    uint16_t* dl = g_wtl + p.dstOff[m];
    const int tot = K * Ncols;
    for (int i = blockIdx.x * blockDim.x + threadIdx.x; i < tot;
         i += gridDim.x * blockDim.x) {
        int k = i / Ncols, n = i % Ncols;
        float v = src[i];
        __nv_bfloat16 hb = __float2bfloat16(v);
        float hf = __bfloat162float(hb);
        __nv_bfloat16 lb = __float2bfloat16(v - hf);
        dh[n * K + k] = *(uint16_t*)&hb;
        dl[n * K + k] = *(uint16_t*)&lb;
    }
}

// ---------------- edge dtype sniff -----------------------------------------
__global__ void k_detect(const int* e32) {
    __shared__ int nz;
    if (threadIdx.x == 0) nz = 0;
    __syncthreads();
    for (int i = threadIdx.x; i < 2048; i += blockDim.x) {
        if (e32[2 * i + 1] != 0) nz = 1;
    }
    __syncthreads();
    if (threadIdx.x == 0) g_fmt64 = (nz == 0) ? 1 : 0;
}

__device__ __forceinline__ int edge_at(const void* e, int idx) {
    if (g_fmt64) return (int)((const long long*)e)[idx];
    return ((const int*)e)[idx];
}

// ---------------- CSR build (2 views per launch, vbase selects group) -------
struct EPtr4 { const void* e[4]; };

__global__ void k_zero_counts(int vbase) {
    int i = blockIdx.x * blockDim.x + threadIdx.x;
    if (i < NN) g_counts[vbase + blockIdx.y][i] = 0;
}

__global__ void k_count(EPtr4 ep, int vbase) {
    int i = blockIdx.x * blockDim.x + threadIdx.x;
    if (i >= EE) return;
    const int v = vbase + blockIdx.y;
    int d = edge_at(ep.e[v], EE + i);
    atomicAdd(&g_counts[v][d], 1);
}

__global__ void k_deg(int vbase) {
    int i = blockIdx.x * blockDim.x + threadIdx.x;
    if (i < NN) {
        int v = vbase + blockIdx.y;
        float dg = (float)(g_counts[v][i] + 1);
        g_dinv[v][i]   = rsqrtf(dg);
        g_deginv[v][i] = 1.0f / dg;
    }
}

__global__ void k_scan(int vbase) {
    const int v = vbase + blockIdx.x;
    __shared__ int sh[1024];
    __shared__ int carry;
    if (threadIdx.x == 0) { carry = 0; g_rowptr[v][0] = 0; }
    __syncthreads();
    for (int base = 0; base < NN; base += 1024) {
        int i = base + threadIdx.x;
        int val = (i < NN) ? g_counts[v][i] : 0;
        sh[threadIdx.x] = val;
        __syncthreads();
        for (int d = 1; d < 1024; d <<= 1) {
            int t = (threadIdx.x >= d) ? sh[threadIdx.x - d] : 0;
            __syncthreads();
            sh[threadIdx.x] += t;
            __syncthreads();
        }
        if (i < NN) {
            g_rowptr[v][i + 1] = carry + sh[threadIdx.x];
            g_cursor[v][i] = 0;
        }
        __syncthreads();
        if (threadIdx.x == 0) carry += sh[1023];
        __syncthreads();
    }
}

__global__ void k_fill(EPtr4 ep, int vbase) {
    int i = blockIdx.x * blockDim.x + threadIdx.x;
    if (i >= EE) return;
    const int v = vbase + blockIdx.y;
    int s = edge_at(ep.e[v], i);
    int d = edge_at(ep.e[v], EE + i);
    int pos = g_rowptr[v][d] + atomicAdd(&g_cursor[v][d], 1);
    g_col[v][pos]  = s;
    g_coef[v][pos] = g_dinv[v][s] * g_dinv[v][d];
}

// ---------------- GCN aggregation + self loop + bias + LeakyReLU ------------
template <int F, bool SPLIT>
__global__ void __launch_bounds__(256)
k_agg(const float* __restrict__ xwAll, Ptr4 bias, float* __restrict__ outAll,
      int vbase) {
    constexpr int TPR = F / 4;
    constexpr int RPB = 256 / TPR;
    const int view = vbase + blockIdx.y;
    const int rid = threadIdx.x / TPR;
    const int f4  = threadIdx.x % TPR;
    const int row = blockIdx.x * RPB + rid;
    if (row >= NN) return;

    const float* __restrict__ xw = xwAll + (size_t)view * NN * F;
    const int* __restrict__ rp   = g_rowptr[view];
    const int* __restrict__ col  = g_col[view];
    const float* __restrict__ cf = g_coef[view];

    const int start = rp[row];
    const int end   = rp[row + 1];
    float4 acc = make_float4(0.f, 0.f, 0.f, 0.f);
    for (int p = start; p < end; p++) {
        const int s    = col[p];
        const float w  = cf[p];
        float4 v = *(const float4*)(xw + (size_t)s * F + f4 * 4);
        acc.x += v.x * w; acc.y += v.y * w;
        acc.z += v.z * w; acc.w += v.w * w;
    }
    const float di = g_deginv[view][row];
    float4 sv = *(const float4*)(xw + (size_t)row * F + f4 * 4);
    float4 bv = *(const float4*)(bias.p[view] + f4 * 4);
    float4 o;
    o.x = acc.x + sv.x * di + bv.x;
    o.y = acc.y + sv.y * di + bv.y;
    o.z = acc.z + sv.z * di + bv.z;
    o.w = acc.w + sv.w * di + bv.w;
    o.x = (o.x >= 0.f) ? o.x : 0.2f * o.x;
    o.y = (o.y >= 0.f) ? o.y : 0.2f * o.y;
    o.z = (o.z >= 0.f) ? o.z : 0.2f * o.z;
    o.w = (o.w >= 0.f) ? o.w : 0.2f * o.w;

    if (SPLIT) {
        uint32_t h0 = pack_bf16(o.x, o.y);
        uint32_t h1 = pack_bf16(o.z, o.w);
        uint32_t l0 = pack_bf16(o.x - bfLO(h0), o.y - bfHI(h0));
        uint32_t l1 = pack_bf16(o.z - bfLO(h1), o.w - bfHI(h1));
        const size_t idx = (size_t)row * (F / 4) + f4;
        g_bh[view][idx] = make_uint2(h0, h1);
        g_bl[view][idx] = make_uint2(l0, l1);
    } else {
        float* __restrict__ out = outAll + (size_t)view * NN * F;
        *(float4*)(out + (size_t)row * F + f4 * 4) = o;
    }
}

// ---------------- final combine (batched over 2 node types) ----------------
struct CArgs { const float* res[2]; const float* rb[2]; };
__global__ void k_combine(const float* __restrict__ outSecs,
                          CArgs ca, float* __restrict__ dst) {
    const int j = blockIdx.y;
    const size_t SEC = (size_t)NN * FOUT;
    const float* jv  = outSecs + (2 + j) * SEC;
    const float* bv  = outSecs + (4 + j) * SEC;
    const float* res = ca.res[j];
    int i = blockIdx.x * blockDim.x + threadIdx.x;
    if (i < NN * FOUT) {
        dst[j * SEC + i] = 0.5f * (jv[i] + bv[i]) + res[i]
                         + ca.rb[j][i & (FOUT - 1)];
    }
}

// ---------------- host orchestration ----------------------------------------
#define GEMM_GRID_X ((NN + 127) / 128)

extern "C" void kernel_launch(void* const* d_in, const int* in_sizes, int n_in,
                              void* d_out, int out_size) {
    const float* x_lj = (const float*)d_in[0];
    const float* x_pj = (const float*)d_in[1];
    const float* x_lb = (const float*)d_in[2];
    const float* x_pb = (const float*)d_in[3];

    EPtr4 ep; ep.e[0] = d_in[4]; ep.e[1] = d_in[5]; ep.e[2] = d_in[6]; ep.e[3] = d_in[7];

    const float* W_j1_l = (const float*)d_in[8];   const float* b_j1_l = (const float*)d_in[9];
    const float* W_j1_p = (const float*)d_in[10];  const float* b_j1_p = (const float*)d_in[11];
    const float* W_j2_l = (const float*)d_in[12];  const float* b_j2_l = (const float*)d_in[13];
    const float* W_j2_p = (const float*)d_in[14];  const float* b_j2_p = (const float*)d_in[15];
    const float* W_b1_l = (const float*)d_in[16];  const float* b_b1_l = (const float*)d_in[17];
    const float* W_b1_p = (const float*)d_in[18];  const float* b_b1_p = (const float*)d_in[19];
    const float* W_b2_l = (const float*)d_in[20];  const float* b_b2_l = (const float*)d_in[21];
    const float* W_b2_p = (const float*)d_in[22];  const float* b_b2_p = (const float*)d_in[23];
    const float* W_r_l  = (const float*)d_in[24];  const float* b_r_l  = (const float*)d_in[25];
    const float* W_r_p  = (const float*)d_in[26];  const float* b_r_p  = (const float*)d_in[27];

    float* out = (float*)d_out;
    const size_t SEC = (size_t)NN * FOUT;

    float *bufA, *bufC;
    uint16_t *xh, *xl, *bh, *bl, *wth, *wtl;
    cudaGetSymbolAddress((void**)&bufA, g_bufA);
    cudaGetSymbolAddress((void**)&bufC, g_bufC);
    cudaGetSymbolAddress((void**)&xh,   g_xh);
    cudaGetSymbolAddress((void**)&xl,   g_xl);
    cudaGetSymbolAddress((void**)&bh,   g_bh);
    cudaGetSymbolAddress((void**)&bl,   g_bl);
    cudaGetSymbolAddress((void**)&wth,  g_wth);
    cudaGetSymbolAddress((void**)&wtl,  g_wtl);

    cudaFuncSetAttribute(k_gemm<256>, cudaFuncAttributeMaxDynamicSharedMemorySize, SMEM_GEMM);
    cudaFuncSetAttribute(k_gemm<128>, cudaFuncAttributeMaxDynamicSharedMemorySize, SMEM_GEMM);

    // fresh stream/events per call (never destroyed: a few objects leak on the
    // 1-2 host invocations; replays run the captured graph and don't re-enter)
    cudaStream_t sB;
    cudaEvent_t eF, eX, eB;
    cudaStreamCreateWithFlags(&sB, cudaStreamNonBlocking);
    cudaEventCreateWithFlags(&eF, cudaEventDisableTiming);
    cudaEventCreateWithFlags(&eX, cudaEventDisableTiming);
    cudaEventCreateWithFlags(&eB, cudaEventDisableTiming);

    const size_t NHID = (size_t)NN * HID;
    const size_t NFIN = (size_t)NN * FIN;
    const size_t NOUT = (size_t)NN * FOUT;
    dim3 gz2((NN + 255) / 256, 2);
    dim3 ge2((EE + 255) / 256, 2);

    // ---- legacy: edge dtype, then fork pipeline B -----------------------
    k_detect<<<1, 256>>>((const int*)ep.e[0]);
    cudaEventRecord(eF, 0);
    cudaStreamWaitEvent(sB, eF, 0);

    // ---- pipeline B (stream sB): CSR for views 2,3 ----------------------
    k_zero_counts<<<gz2, 256, 0, sB>>>(2);
    k_count<<<ge2, 256, 0, sB>>>(ep, 2);
    k_deg<<<gz2, 256, 0, sB>>>(2);
    k_scan<<<2, 1024, 0, sB>>>(2);
    k_fill<<<ge2, 256, 0, sB>>>(ep, 2);

    // ---- legacy (pipeline A): prep shared data ---------------------------
    Ptr4 ax; ax.p[0] = x_lj; ax.p[1] = x_pj; ax.p[2] = x_lb; ax.p[3] = x_pb;
    k_splitx<<<dim3((NN * FIN / 4 + 255) / 256, 4), 256>>>(ax);

    TPars tp;
    const float* ws[10] = {W_j1_l, W_j1_p, W_b1_l, W_b1_p,
                           W_j2_l, W_j2_p, W_b2_l, W_b2_p, W_r_l, W_r_p};
    for (int m = 0; m < 10; m++) {
        tp.src[m] = ws[m];
        tp.K[m] = 256;
        tp.N[m] = (m < 4) ? 256 : 128;
        tp.dstOff[m] = (m < 4) ? m * 65536 : 4 * 65536 + (m - 4) * 32768;
    }
    k_transpose_all<<<dim3(64, 10), 256>>>(tp);
    cudaEventRecord(eX, 0);
    cudaStreamWaitEvent(sB, eX, 0);      // B needs splitx + weights

    // ---- pipeline A: CSR for views 0,1 -----------------------------------
    k_zero_counts<<<gz2, 256>>>(0);
    k_count<<<ge2, 256>>>(ep, 0);
    k_deg<<<gz2, 256>>>(0);
    k_scan<<<2, 1024>>>(0);
    k_fill<<<ge2, 256>>>(ep, 0);

    const uint16_t* w2base_h = wth + 4 * 65536;
    const uint16_t* w2base_l = wtl + 4 * 65536;

    // ---- pipeline B compute (views 2,3 + residual_p) ----------------------
    {
        GArgs g1;
        for (int j = 0; j < 2; j++) {
            int v = 2 + j;
            g1.ah[j] = xh + (size_t)v * NFIN;  g1.al[j] = xl + (size_t)v * NFIN;
            g1.wh[j] = wth + v * 65536;        g1.wl[j] = wtl + v * 65536;
            g1.c[j]  = bufA + (size_t)v * NHID;
        }
        g1.ah[2] = g1.ah[0]; g1.al[2] = g1.al[0];
        g1.wh[2] = g1.wh[0]; g1.wl[2] = g1.wl[0]; g1.c[2] = g1.c[0];
        k_gemm<256><<<dim3(GEMM_GRID_X, 2, 2), 256, SMEM_GEMM, sB>>>(g1, NN);

        Ptr4 b1; b1.p[0] = b_j1_l; b1.p[1] = b_j1_p; b1.p[2] = b_b1_l; b1.p[3] = b_b1_p;
        k_agg<HID, true><<<dim3((NN + 3) / 4, 2), 256, 0, sB>>>(bufA, b1, nullptr, 2);

        GArgs g2;
        for (int j = 0; j < 2; j++) {
            int v = 2 + j;
            g2.ah[j] = bh + (size_t)v * NHID;  g2.al[j] = bl + (size_t)v * NHID;
            g2.wh[j] = w2base_h + v * 32768;   g2.wl[j] = w2base_l + v * 32768;
            g2.c[j]  = bufC + (size_t)v * NOUT;
        }
        // residual_p: A = x_pj (view 1 split), W = W_r_p (slot 5); out -> bufA[2]
        g2.ah[2] = xh + 1 * NFIN;  g2.al[2] = xl + 1 * NFIN;
        g2.wh[2] = w2base_h + 5 * 32768;  g2.wl[2] = w2base_l + 5 * 32768;
        g2.c[2]  = bufA + 2 * NHID;       // bufA[2] free after B's agg1
        k_gemm<128><<<dim3(GEMM_GRID_X, 1, 3), 256, SMEM_GEMM, sB>>>(g2, NN);

        Ptr4 b2; b2.p[0] = b_j2_l; b2.p[1] = b_j2_p; b2.p[2] = b_b2_l; b2.p[3] = b_b2_p;
        // sections 2..5 of out correspond to views 0..3
        k_agg<FOUT, false><<<dim3((NN + 7) / 8, 2), 256, 0, sB>>>(
            bufC, b2, out + 2 * SEC, 2);
        cudaEventRecord(eB, sB);
    }

    // ---- pipeline A compute (views 0,1 + residual_l) ----------------------
    {
        GArgs g1;
        for (int j = 0; j < 2; j++) {
            g1.ah[j] = xh + (size_t)j * NFIN;  g1.al[j] = xl + (size_t)j * NFIN;
            g1.wh[j] = wth + j * 65536;        g1.wl[j] = wtl + j * 65536;
            g1.c[j]  = bufA + (size_t)j * NHID;
        }
        g1.ah[2] = g1.ah[0]; g1.al[2] = g1.al[0];
        g1.wh[2] = g1.wh[0]; g1.wl[2] = g1.wl[0]; g1.c[2] = g1.c[0];
        k_gemm<256><<<dim3(GEMM_GRID_X, 2, 2), 256, SMEM_GEMM>>>(g1, NN);

        Ptr4 b1; b1.p[0] = b_j1_l; b1.p[1] = b_j1_p; b1.p[2] = b_b1_l; b1.p[3] = b_b1_p;
        k_agg<HID, true><<<dim3((NN + 3) / 4, 2), 256>>>(bufA, b1, nullptr, 0);

        GArgs g2;
        for (int j = 0; j < 2; j++) {
            g2.ah[j] = bh + (size_t)j * NHID;  g2.al[j] = bl + (size_t)j * NHID;
            g2.wh[j] = w2base_h + j * 32768;   g2.wl[j] = w2base_l + j * 32768;
            g2.c[j]  = bufC + (size_t)j * NOUT;
        }
        // residual_l: A = x_lj (view 0 split), W = W_r_l (slot 4); out -> bufA[0]
        g2.ah[2] = xh;  g2.al[2] = xl;
        g2.wh[2] = w2base_h + 4 * 32768;  g2.wl[2] = w2base_l + 4 * 32768;
        g2.c[2]  = bufA;                  // bufA[0] free after A's agg1
        k_gemm<128><<<dim3(GEMM_GRID_X, 1, 3), 256, SMEM_GEMM>>>(g2, NN);

        Ptr4 b2; b2.p[0] = b_j2_l; b2.p[1] = b_j2_p; b2.p[2] = b_b2_l; b2.p[3] = b_b2_p;
        k_agg<FOUT, false><<<dim3((NN + 7) / 8, 2), 256>>>(
            bufC, b2, out + 2 * SEC, 0);
    }

    // ---- join and combine -------------------------------------------------
    cudaStreamWaitEvent(0, eB, 0);
    CArgs ca;
    ca.res[0] = bufA;                 // residual_l
    ca.res[1] = bufA + 2 * NHID;      // residual_p
    ca.rb[0] = b_r_l; ca.rb[1] = b_r_p;
    k_combine<<<dim3((NN * FOUT + 255) / 256, 2), 256>>>(out, ca, out);
}